// round 14
// baseline (speedup 1.0000x reference)
#include <cuda_runtime.h>
#include <cuda_fp16.h>
#include <math.h>
#include <stdint.h>

#define T 2048
#define D 2048
#define NH 16
#define NKVH 4
#define HD 128
#define DH 1024
#define KVD 512
#define MEG (1024*1024)

__device__ float g_scratch[25 * MEG];

// ================= PTX helpers =================
__device__ __forceinline__ uint32_t smem_u32(const void* p) {
    uint32_t a;
    asm("{ .reg .u64 t; cvta.to.shared.u64 t, %1; cvt.u32.u64 %0, t; }" : "=r"(a) : "l"(p));
    return a;
}
#define CP16(s, g) asm volatile("cp.async.cg.shared.global [%0], [%1], 16;" \
    :: "r"(s), "l"(__cvta_generic_to_global(g)) : "memory")
#define CP_COMMIT() asm volatile("cp.async.commit_group;" ::: "memory")
#define CP_WAIT(n)  asm volatile("cp.async.wait_group %0;" :: "n"(n) : "memory")

__device__ __forceinline__ void ldsm_x4(uint32_t* r, uint32_t addr) {
    asm volatile("ldmatrix.sync.aligned.m8n8.x4.shared.b16 {%0,%1,%2,%3}, [%4];"
        : "=r"(r[0]), "=r"(r[1]), "=r"(r[2]), "=r"(r[3]) : "r"(addr));
}
__device__ __forceinline__ void ldsm_x4_t(uint32_t* r, uint32_t addr) {
    asm volatile("ldmatrix.sync.aligned.m8n8.x4.trans.shared.b16 {%0,%1,%2,%3}, [%4];"
        : "=r"(r[0]), "=r"(r[1]), "=r"(r[2]), "=r"(r[3]) : "r"(addr));
}
__device__ __forceinline__ void mma16816(float* d, const uint32_t* a, uint32_t b0, uint32_t b1) {
    asm volatile("mma.sync.aligned.m16n8k16.row.col.f32.f16.f16.f32 "
        "{%0,%1,%2,%3}, {%4,%5,%6,%7}, {%8,%9}, {%0,%1,%2,%3};"
        : "+f"(d[0]), "+f"(d[1]), "+f"(d[2]), "+f"(d[3])
        : "r"(a[0]), "r"(a[1]), "r"(a[2]), "r"(a[3]), "r"(b0), "r"(b1));
}
__device__ __forceinline__ float ex2(float x) {
    float y; asm("ex2.approx.ftz.f32 %0, %1;" : "=f"(y) : "f"(x)); return y;
}
__device__ __forceinline__ uint32_t pk2(float a, float b) {
    __half2 h = __floats2half2_rn(a, b);
    return *(uint32_t*)&h;
}

// ================= mega-prep: ema1 + hs->fp16 + 5 weight transposes =========
__global__ void prep_kernel(const float* __restrict__ hs,
                            const float* __restrict__ Wq, const float* __restrict__ Wr1,
                            const float* __restrict__ Wk, const float* __restrict__ Wv,
                            const float* __restrict__ Wo,
                            __half* __restrict__ WqT, __half* __restrict__ Wr1T,
                            __half* __restrict__ WkT, __half* __restrict__ WvT,
                            __half* __restrict__ WoT,
                            __half* __restrict__ hsH, float* __restrict__ l2,
                            float* __restrict__ carry) {
    __shared__ float tile[32][33];
    int lb = blockIdx.x;
    int tid = threadIdx.x;
    if (lb < 128) {            // ema1 (latency-bound; scheduled first)
        int c = lb >> 3;
        int d = (lb & 7) * 256 + tid;
        float m = 0.f;
        int t0 = c * 128;
        for (int t = t0; t < t0 + 128; t++) {
            m = 0.9f * m + 0.1f * hs[(size_t)t * D + d];
            l2[(size_t)t * D + d] = m;
        }
        carry[c * D + d] = m;
        return;
    }
    lb -= 128;
    if (lb < 4096) {           // hs -> fp16
        int i = lb * 256 + tid;
        float4 a = ((const float4*)hs)[i];
        ((uint32_t*)hsH)[2 * i]     = pk2(a.x, a.y);
        ((uint32_t*)hsH)[2 * i + 1] = pk2(a.z, a.w);
        return;
    }
    lb -= 4096;
    const float* W; __half* Wt; int Kd, Nd;
    if (lb < 4096)      { W = Wq;  Wt = WqT;  Kd = D; Nd = D;   }
    else if (lb < 6144) { W = Wr1; Wt = Wr1T; Kd = D; Nd = DH;  lb -= 4096; }
    else if (lb < 7168) { W = Wk;  Wt = WkT;  Kd = D; Nd = KVD; lb -= 6144; }
    else if (lb < 8192) { W = Wv;  Wt = WvT;  Kd = D; Nd = KVD; lb -= 7168; }
    else                { W = Wo;  Wt = WoT;  Kd = D; Nd = D;   lb -= 8192; }
    int ntn = Nd / 32;
    int nb = (lb % ntn) * 32, kb = (lb / ntn) * 32;
    int tx = tid & 31, ty0 = tid >> 5;
    #pragma unroll
    for (int i = 0; i < 4; i++)
        tile[ty0 + 8 * i][tx] = W[(size_t)(kb + ty0 + 8 * i) * Nd + nb + tx];
    __syncthreads();
    #pragma unroll
    for (int i = 0; i < 4; i++) {
        int r = ty0 + 8 * i;
        Wt[(size_t)(nb + r) * Kd + kb + tx] = __float2half_rn(tile[tx][r]);
    }
}

// ================= EMA pass 2 =================
__global__ void ema2_kernel(const float* __restrict__ carry, float* __restrict__ cpref) {
    int d = blockIdx.x * 256 + threadIdx.x;
    const float b128 = 1.3900845e-06f;  // 0.9^128
    float p = 0.f;
    #pragma unroll
    for (int c = 0; c < 16; c++) {
        cpref[c * D + d] = p;
        p = carry[c * D + d] + b128 * p;
    }
}

// ================= fp16 HMMA GEMM, triple-buffered, occ 2 =================
#define SM_STRIDE 80
#define SM_SPLIT 10240
#define SM_BUF 20480
#define SMEMB 61440

template<int ACT>
__global__ __launch_bounds__(256, 2)
void gemm_mma(const __half* __restrict__ A, const __half* __restrict__ B,
              const float* __restrict__ bias, float* __restrict__ C,
              __half* __restrict__ Chi,
              int M, int N, int K,
              const __half* B2, float* C2, __half* C2hi) {
    extern __shared__ char smem[];
    if (blockIdx.z) { B = B2; C = C2; Chi = C2hi; }
    const int tid = threadIdx.x, wid = tid >> 5, lane = tid & 31;
    const int m0 = blockIdx.y * 128, n0 = blockIdx.x * 128;
    const int wm = wid >> 2, wn = wid & 3;
    const uint32_t sb = smem_u32(smem);

    const int r0c = tid >> 2, c0c = (tid & 3);
    const int r1c = (tid + 256) >> 2, c1c = (tid & 3);

    auto fill = [&](int buf, int kc) {
        const int k0 = kc << 5;
        const uint32_t s0 = sb + buf * SM_BUF;
        uint32_t so0 = r0c * SM_STRIDE + c0c * 16;
        uint32_t so1 = r1c * SM_STRIDE + c1c * 16;
        CP16(s0 + so0, A + (size_t)(m0 + r0c) * K + k0 + c0c * 8);
        CP16(s0 + so1, A + (size_t)(m0 + r1c) * K + k0 + c1c * 8);
        CP16(s0 + SM_SPLIT + so0, B + (size_t)(n0 + r0c) * K + k0 + c0c * 8);
        CP16(s0 + SM_SPLIT + so1, B + (size_t)(n0 + r1c) * K + k0 + c1c * 8);
        CP_COMMIT();
    };

    float acc[4][4][4] = {};
    const int KC = K >> 5;
    fill(0, 0);
    if (KC > 1) fill(1, 1);
    for (int kc = 0; kc < KC; kc++) {
        if (kc + 2 < KC) { fill((kc + 2) % 3, kc + 2); CP_WAIT(2); }
        else if (kc + 1 < KC) { CP_WAIT(1); }
        else { CP_WAIT(0); }
        __syncthreads();
        const uint32_t base = sb + (kc % 3) * SM_BUF;
        const uint32_t lrow = (lane & 15), lcol = (lane >> 4) * 16;
        #pragma unroll
        for (int kh = 0; kh < 2; kh++) {
            uint32_t af[4][4], bf[2][4];
            #pragma unroll
            for (int mt = 0; mt < 4; mt++)
                ldsm_x4(af[mt], base + (wm * 64 + mt * 16 + lrow) * SM_STRIDE + kh * 32 + lcol);
            #pragma unroll
            for (int nt = 0; nt < 2; nt++)
                ldsm_x4(bf[nt], base + SM_SPLIT + (wn * 32 + nt * 16 + lrow) * SM_STRIDE + kh * 32 + lcol);
            #pragma unroll
            for (int mt = 0; mt < 4; mt++)
                #pragma unroll
                for (int j = 0; j < 4; j++)
                    mma16816(acc[mt][j], af[mt], bf[j >> 1][j & 1], bf[j >> 1][2 + (j & 1)]);
        }
        __syncthreads();
    }

    const int erow = m0 + wm * 64 + (lane >> 2);
    const int ecol = n0 + wn * 32 + (lane & 3) * 2;
    #pragma unroll
    for (int mt = 0; mt < 4; mt++)
        #pragma unroll
        for (int j = 0; j < 4; j++) {
            int r = erow + mt * 16, c = ecol + j * 8;
            float v0 = acc[mt][j][0], v1 = acc[mt][j][1];
            float v2 = acc[mt][j][2], v3 = acc[mt][j][3];
            if (ACT) {
                float b0 = bias[c], b1 = bias[c + 1];
                v0 += b0; v1 += b1; v2 += b0; v3 += b1;
                v0 = v0 / (1.f + expf(-v0)); v1 = v1 / (1.f + expf(-v1));
                v2 = v2 / (1.f + expf(-v2)); v3 = v3 / (1.f + expf(-v3));
            }
            if (C) {
                *(float2*)(C + (size_t)r * N + c)       = make_float2(v0, v1);
                *(float2*)(C + (size_t)(r + 8) * N + c) = make_float2(v2, v3);
            }
            if (Chi) {
                *(uint32_t*)(Chi + (size_t)r * N + c)       = pk2(v0, v1);
                *(uint32_t*)(Chi + (size_t)(r + 8) * N + c) = pk2(v2, v3);
            }
        }
}

// ================= router + fuse (one block per token) =================
__global__ void router_fuse(const float* __restrict__ h, const float* __restrict__ Wr2,
                            const float* __restrict__ br2, const float* __restrict__ x,
                            const float* __restrict__ l2, const float* __restrict__ cpref,
                            __half* __restrict__ fh) {
    __shared__ float red[16];
    __shared__ float lamS[2];
    int t = blockIdx.x, tid = threadIdx.x, wid = tid >> 5, lane = tid & 31;
    const float* hp = h + (size_t)t * DH;
    float4 hv  = *(const float4*)(hp + tid * 4);
    float4 w01 = *(const float4*)(Wr2 + tid * 8);
    float4 w23 = *(const float4*)(Wr2 + tid * 8 + 4);
    float z0 = hv.x * w01.x + hv.y * w01.z + hv.z * w23.x + hv.w * w23.z;
    float z1 = hv.x * w01.y + hv.y * w01.w + hv.z * w23.y + hv.w * w23.w;
    #pragma unroll
    for (int off = 16; off; off >>= 1) {
        z0 += __shfl_xor_sync(0xffffffffu, z0, off);
        z1 += __shfl_xor_sync(0xffffffffu, z1, off);
    }
    if (lane == 0) { red[wid] = z0; red[8 + wid] = z1; }
    __syncthreads();
    if (tid == 0) {
        float a = 0.f, b = 0.f;
        #pragma unroll
        for (int i = 0; i < 8; i++) { a += red[i]; b += red[8 + i]; }
        a += br2[0]; b += br2[1];
        float mx = fmaxf(a, b);
        float e0 = expf(a - mx), e1 = expf(b - mx);
        float inv = 1.f / (e0 + e1);
        lamS[0] = e0 * inv; lamS[1] = e1 * inv;
    }
    __syncthreads();
    float la = lamS[0], lb = lamS[1];
    int c = t >> 7, tl = t & 127;
    float w = __expf((float)(tl + 1) * -0.10536051565f);
    size_t rowo = (size_t)t * D;
    #pragma unroll
    for (int i = 0; i < 2; i++) {
        int e = tid * 8 + i * 4;
        float4 xv = *(const float4*)(x + rowo + e);
        float4 lv = *(const float4*)(l2 + rowo + e);
        float4 cp = *(const float4*)(cpref + c * D + e);
        float f0 = la * xv.x + lb * (lv.x + w * cp.x);
        float f1 = la * xv.y + lb * (lv.y + w * cp.y);
        float f2 = la * xv.z + lb * (lv.z + w * cp.z);
        float f3 = la * xv.w + lb * (lv.w + w * cp.w);
        ((uint32_t*)fh)[(rowo + e) / 2]     = pk2(f0, f1);
        ((uint32_t*)fh)[(rowo + e) / 2 + 1] = pk2(f2, f3);
    }
}

// ================= RoPE (fp16 in, fp16 out) =================
__global__ void rope_h(const __half* __restrict__ x, __half* __restrict__ o, int heads) {
    int idx = blockIdx.x * blockDim.x + threadIdx.x;
    int total = T * heads * 32;
    if (idx >= total) return;
    int jp = idx & 31;
    int hh = (idx >> 5) % heads;
    int t = idx / (heads * 32);
    int j = jp * 2;
    const float LN = 0.1439115683121279f;  // ln(10000)/64
    float inv0 = expf(-LN * j), inv1 = expf(-LN * (j + 1));
    float c0, s0, c1, s1;
    sincosf((float)t * inv0, &s0, &c0);
    sincosf((float)t * inv1, &s1, &c1);
    size_t base = (size_t)t * heads * HD + hh * HD;
    __half2 plo = *(const __half2*)(x + base + j);
    __half2 phi = *(const __half2*)(x + base + j + 64);
    float a0 = __low2float(plo), a1 = __high2float(plo);
    float b0 = __low2float(phi), b1 = __high2float(phi);
    *(uint32_t*)(o + base + j)      = pk2(a0 * c0 - b0 * s0, a1 * c1 - b1 * s1);
    *(uint32_t*)(o + base + j + 64) = pk2(b0 * c0 + a0 * s0, b1 * c1 + a1 * s1);
}

// ===== tensor-core flash attention (256 thr, 128-row Q tile, pure fp16) =====
#define FA_STR 272
#define FA_QS 34816
#define FA_KS 17408
#define FA_KVB 34816
#define FA_KV0 34816
#define FA_SMEM 104448

__global__ __launch_bounds__(256, 1)
void fattn_kernel(const __half* __restrict__ Q, const __half* __restrict__ K,
                  const __half* __restrict__ V, __half* __restrict__ aoH) {
    extern __shared__ char smem[];
    const int tid = threadIdx.x, wid = tid >> 5, lane = tid & 31;
    const int qt = (int)(gridDim.x - 1 - blockIdx.x);   // long CTAs first
    const int head = blockIdx.y;
    const int kvh = head >> 2;
    const uint32_t sb = smem_u32(smem);
    const int g = lane >> 2, tq = lane & 3;
    const uint32_t lrow = lane & 15, lcol = (lane >> 4) * 16;

    {
        const size_t qoff = (size_t)(qt * 128) * D + head * HD;
        #pragma unroll
        for (int i = 0; i < 8; i++) {
            int idx = tid + i * 256;
            int r = idx >> 4, c = idx & 15;
            CP16(sb + r * FA_STR + c * 16, Q + qoff + (size_t)r * D + c * 8);
        }
        CP_COMMIT();
    }

    const int kts = 2 * qt + 2;
    auto loadKV = [&](int kt) {
        const size_t koff = (size_t)(kt * 64) * KVD + kvh * HD;
        const uint32_t kb = sb + FA_KV0 + (kt & 1) * FA_KVB;
        #pragma unroll
        for (int i = 0; i < 4; i++) {
            int idx = tid + i * 256;
            int r = idx >> 4, c = idx & 15;
            size_t so = koff + (size_t)r * KVD + c * 8;
            uint32_t dst = kb + r * FA_STR + c * 16;
            CP16(dst,         K + so);
            CP16(dst + FA_KS, V + so);
        }
        CP_COMMIT();
    };
    loadKV(0);

    float m0 = -1e30f, m1 = -1e30f, l0 = 0.f, l1 = 0.f;
    float oa[16][4] = {};
    const float SC2 = 0.08838834764831845f * 1.4426950408889634f;

    for (int kt = 0; kt < kts; kt++) {
        if (kt + 1 < kts) { loadKV(kt + 1); CP_WAIT(1); }
        else              { CP_WAIT(0); }
        __syncthreads();
        const uint32_t kb = sb + FA_KV0 + (kt & 1) * FA_KVB;

        float s[8][4];
        #pragma unroll
        for (int nf = 0; nf < 8; nf++)
            s[nf][0] = s[nf][1] = s[nf][2] = s[nf][3] = 0.f;
        #pragma unroll
        for (int ks = 0; ks < 8; ks++) {
            uint32_t af[4], bk[4][4];
            ldsm_x4(af, sb + (wid * 16 + lrow) * FA_STR + lcol + ks * 32);
            #pragma unroll
            for (int bt = 0; bt < 4; bt++)
                ldsm_x4(bk[bt], kb + (bt * 16 + lrow) * FA_STR + lcol + ks * 32);
            #pragma unroll
            for (int nf = 0; nf < 8; nf++)
                mma16816(s[nf], af, bk[nf >> 1][nf & 1], bk[nf >> 1][2 + (nf & 1)]);
        }

        if (kt >= kts - 2) {
            int rg = qt * 128 + wid * 16 + g;
            int kbase = kt * 64;
            #pragma unroll
            for (int nf = 0; nf < 8; nf++) {
                int cg = kbase + nf * 8 + tq * 2;
                if (cg > rg)         s[nf][0] = -1e30f;
                if (cg + 1 > rg)     s[nf][1] = -1e30f;
                if (cg > rg + 8)     s[nf][2] = -1e30f;
                if (cg + 1 > rg + 8) s[nf][3] = -1e30f;
            }
        }

        float mx0 = -1e30f, mx1 = -1e30f;
        #pragma unroll
        for (int nf = 0; nf < 8; nf++) {
            mx0 = fmaxf(mx0, fmaxf(s[nf][0], s[nf][1]));
            mx1 = fmaxf(mx1, fmaxf(s[nf][2], s[nf][3]));
        }
        mx0 = fmaxf(mx0, __shfl_xor_sync(0xffffffffu, mx0, 1));
        mx0 = fmaxf(mx0, __shfl_xor_sync(0xffffffffu, mx0, 2));
        mx1 = fmaxf(mx1, __shfl_xor_sync(0xffffffffu, mx1, 1));
        mx1 = fmaxf(mx1, __shfl_xor_sync(0xffffffffu, mx1, 2));
        float mn0 = fmaxf(m0, mx0), mn1 = fmaxf(m1, mx1);
        float corr0 = ex2((m0 - mn0) * SC2);
        float corr1 = ex2((m1 - mn1) * SC2);
        m0 = mn0; m1 = mn1;
        l0 *= corr0; l1 *= corr1;
        #pragma unroll
        for (int nf = 0; nf < 8; nf++) {
            s[nf][0] = ex2((s[nf][0] - m0) * SC2);
            s[nf][1] = ex2((s[nf][1] - m0) * SC2);
            s[nf][2] = ex2((s[nf][2] - m1) * SC2);
            s[nf][3] = ex2((s[nf][3] - m1) * SC2);
            l0 += s[nf][0] + s[nf][1];
            l1 += s[nf][2] + s[nf][3];
        }
        #pragma unroll
        for (int nf = 0; nf < 16; nf++) {
            oa[nf][0] *= corr0; oa[nf][1] *= corr0;
            oa[nf][2] *= corr1; oa[nf][3] *= corr1;
        }

        const uint32_t vb = kb + FA_KS;
        #pragma unroll
        for (int pk = 0; pk < 4; pk++) {
            uint32_t pa[4];
            pa[0] = pk2(s[2 * pk][0],     s[2 * pk][1]);
            pa[1] = pk2(s[2 * pk][2],     s[2 * pk][3]);
            pa[2] = pk2(s[2 * pk + 1][0], s[2 * pk + 1][1]);
            pa[3] = pk2(s[2 * pk + 1][2], s[2 * pk + 1][3]);
            #pragma unroll
            for (int nbp = 0; nbp < 4; nbp++) {
                int nb0 = 2 * nbp, nb1 = 2 * nbp + 1;
                uint32_t vh0[4], vh1[4];
                ldsm_x4_t(vh0, vb + (pk * 16 + lrow) * FA_STR + nb0 * 32 + lcol);
                ldsm_x4_t(vh1, vb + (pk * 16 + lrow) * FA_STR + nb1 * 32 + lcol);
                mma16816(oa[2 * nb0],     pa, vh0[0], vh0[1]);
                mma16816(oa[2 * nb0 + 1], pa, vh0[2], vh0[3]);
                mma16816(oa[2 * nb1],     pa, vh1[0], vh1[1]);
                mma16816(oa[2 * nb1 + 1], pa, vh1[2], vh1[3]);
            }
        }
        __syncthreads();
    }

    l0 += __shfl_xor_sync(0xffffffffu, l0, 1);
    l0 += __shfl_xor_sync(0xffffffffu, l0, 2);
    l1 += __shfl_xor_sync(0xffffffffu, l1, 1);
    l1 += __shfl_xor_sync(0xffffffffu, l1, 2);
    float inv0 = 1.f / l0, inv1 = 1.f / l1;
    int row0 = qt * 128 + wid * 16 + g;
    size_t base0 = (size_t)row0 * D + head * HD + tq * 2;
    size_t base1 = base0 + 8 * D;
    #pragma unroll
    for (int nf = 0; nf < 16; nf++) {
        *(uint32_t*)(aoH + base0 + nf * 8) = pk2(oa[nf][0] * inv0, oa[nf][1] * inv0);
        *(uint32_t*)(aoH + base1 + nf * 8) = pk2(oa[nf][2] * inv1, oa[nf][3] * inv1);
    }
}

// ================= launcher =================
extern "C" void kernel_launch(void* const* d_in, const int* in_sizes, int n_in,
                              void* d_out, int out_size) {
    const float* hs  = (const float*)d_in[0];
    const float* Wq  = (const float*)d_in[1];
    const float* Wk  = (const float*)d_in[2];
    const float* Wv  = (const float*)d_in[3];
    const float* Wo  = (const float*)d_in[4];
    const float* Wr1 = (const float*)d_in[5];
    const float* br1 = (const float*)d_in[6];
    const float* Wr2 = (const float*)d_in[7];
    const float* br2 = (const float*)d_in[8];
    float* out = (float*)d_out;

    float* S;
    cudaGetSymbolAddress((void**)&S, g_scratch);
    float* l2    = S;                        // [0,4M)
    float* h     = S + 4 * MEG;              // [4M,6M)
    float* lam   = S + 6 * MEG;
    float* carry = lam + 4096;
    float* cpref = carry + 32768;
    __half* hsH  = (__half*)(S + 7 * MEG);
    __half* qH   = (__half*)(S + 9 * MEG);
    __half* fusH = (__half*)(S + 11 * MEG);
    __half* WqT  = (__half*)(S + 13 * MEG);
    __half* Wr1T = (__half*)(S + 15 * MEG);
    __half* WkT  = (__half*)(S + 16 * MEG);
    __half* WvT  = (__half*)(S + 16 * MEG + 512 * 1024);
    __half* WoT  = (__half*)(S + 17 * MEG);
    __half* kH   = (__half*)(S + 19 * MEG);
    __half* VH   = (__half*)(S + 19 * MEG + 512 * 1024);
    __half* QrH  = (__half*)(S + 20 * MEG);
    __half* KrH  = (__half*)(S + 22 * MEG);
    __half* aoH  = (__half*)(S + 23 * MEG);

    cudaFuncSetAttribute(gemm_mma<0>, cudaFuncAttributeMaxDynamicSharedMemorySize, SMEMB);
    cudaFuncSetAttribute(gemm_mma<1>, cudaFuncAttributeMaxDynamicSharedMemorySize, SMEMB);
    cudaFuncSetAttribute(fattn_kernel, cudaFuncAttributeMaxDynamicSharedMemorySize, FA_SMEM);

    // ---- prep: ema1 + hs fp16 + all weight transposes (one launch) ----
    prep_kernel<<<16512, 256>>>(hs, Wq, Wr1, Wk, Wv, Wo,
                                WqT, Wr1T, WkT, WvT, WoT, hsH, l2, carry);
    ema2_kernel<<<8, 256>>>(carry, cpref);

    // ---- q = hs @ Wq (fp16 out only) ----
    gemm_mma<0><<<dim3(D / 128, T / 128, 1), 256, SMEMB>>>(
        hsH, WqT, nullptr, nullptr, qH, T, D, D, nullptr, nullptr, nullptr);

    // ---- h = silu(q @ Wr1 + br1) (fp32 out) ----
    gemm_mma<1><<<dim3(DH / 128, T / 128, 1), 256, SMEMB>>>(
        qH, Wr1T, br1, h, nullptr, T, DH, D, nullptr, nullptr, nullptr);

    // ---- router + fuse -> fp16 fused ----
    router_fuse<<<T, 256>>>(h, Wr2, br2, hs, l2, cpref, fusH);

    // ---- k/v = fused @ Wk/Wv (fp16 out only) ----
    gemm_mma<0><<<dim3(KVD / 128, T / 128, 2), 256, SMEMB>>>(
        fusH, WkT, nullptr, nullptr, kH, T, KVD, D, WvT, nullptr, VH);

    // ---- RoPE (fp16 in/out) ----
    rope_h<<<(T * NH * 32 + 255) / 256, 256>>>(qH, QrH, NH);
    rope_h<<<(T * NKVH * 32 + 255) / 256, 256>>>(kH, KrH, NKVH);

    // ---- flash attention -> fp16 aoH ----
    fattn_kernel<<<dim3(T / 128, NH), 256, FA_SMEM>>>(QrH, KrH, VH, aoH);

    // ---- out = ao @ Wo (fp32 out) ----
    gemm_mma<0><<<dim3(D / 128, T / 128, 1), 256, SMEMB>>>(
        aoH, WoT, nullptr, out, nullptr, T, D, D, nullptr, nullptr, nullptr);
}

// round 15
// speedup vs baseline: 1.0318x; 1.0318x over previous
#include <cuda_runtime.h>
#include <cuda_fp16.h>
#include <math.h>
#include <stdint.h>

#define T 2048
#define D 2048
#define NH 16
#define NKVH 4
#define HD 128
#define DH 1024
#define KVD 512
#define MEG (1024*1024)

__device__ float g_scratch[25 * MEG];

// ================= PTX helpers =================
__device__ __forceinline__ uint32_t smem_u32(const void* p) {
    uint32_t a;
    asm("{ .reg .u64 t; cvta.to.shared.u64 t, %1; cvt.u32.u64 %0, t; }" : "=r"(a) : "l"(p));
    return a;
}
#define CP16(s, g) asm volatile("cp.async.cg.shared.global [%0], [%1], 16;" \
    :: "r"(s), "l"(__cvta_generic_to_global(g)) : "memory")
#define CP_COMMIT() asm volatile("cp.async.commit_group;" ::: "memory")
#define CP_WAIT(n)  asm volatile("cp.async.wait_group %0;" :: "n"(n) : "memory")

__device__ __forceinline__ void ldsm_x4(uint32_t* r, uint32_t addr) {
    asm volatile("ldmatrix.sync.aligned.m8n8.x4.shared.b16 {%0,%1,%2,%3}, [%4];"
        : "=r"(r[0]), "=r"(r[1]), "=r"(r[2]), "=r"(r[3]) : "r"(addr));
}
__device__ __forceinline__ void ldsm_x4_t(uint32_t* r, uint32_t addr) {
    asm volatile("ldmatrix.sync.aligned.m8n8.x4.trans.shared.b16 {%0,%1,%2,%3}, [%4];"
        : "=r"(r[0]), "=r"(r[1]), "=r"(r[2]), "=r"(r[3]) : "r"(addr));
}
__device__ __forceinline__ void mma16816(float* d, const uint32_t* a, uint32_t b0, uint32_t b1) {
    asm volatile("mma.sync.aligned.m16n8k16.row.col.f32.f16.f16.f32 "
        "{%0,%1,%2,%3}, {%4,%5,%6,%7}, {%8,%9}, {%0,%1,%2,%3};"
        : "+f"(d[0]), "+f"(d[1]), "+f"(d[2]), "+f"(d[3])
        : "r"(a[0]), "r"(a[1]), "r"(a[2]), "r"(a[3]), "r"(b0), "r"(b1));
}
__device__ __forceinline__ float ex2(float x) {
    float y; asm("ex2.approx.ftz.f32 %0, %1;" : "=f"(y) : "f"(x)); return y;
}
__device__ __forceinline__ uint32_t pk2(float a, float b) {
    __half2 h = __floats2half2_rn(a, b);
    return *(uint32_t*)&h;
}

// ================= mega-prep: ema1 + hs->fp16 + 5 weight transposes =========
__global__ void prep_kernel(const float* __restrict__ hs,
                            const float* __restrict__ Wq, const float* __restrict__ Wr1,
                            const float* __restrict__ Wk, const float* __restrict__ Wv,
                            const float* __restrict__ Wo,
                            __half* __restrict__ WqT, __half* __restrict__ Wr1T,
                            __half* __restrict__ WkT, __half* __restrict__ WvT,
                            __half* __restrict__ WoT,
                            __half* __restrict__ hsH, float* __restrict__ l2,
                            float* __restrict__ carry) {
    __shared__ float tile[32][33];
    int lb = blockIdx.x;
    int tid = threadIdx.x;
    if (lb < 128) {            // ema1 (latency-bound; scheduled first)
        int c = lb >> 3;
        int d = (lb & 7) * 256 + tid;
        float m = 0.f;
        int t0 = c * 128;
        for (int t = t0; t < t0 + 128; t++) {
            m = 0.9f * m + 0.1f * hs[(size_t)t * D + d];
            l2[(size_t)t * D + d] = m;
        }
        carry[c * D + d] = m;
        return;
    }
    lb -= 128;
    if (lb < 4096) {           // hs -> fp16
        int i = lb * 256 + tid;
        float4 a = ((const float4*)hs)[i];
        ((uint32_t*)hsH)[2 * i]     = pk2(a.x, a.y);
        ((uint32_t*)hsH)[2 * i + 1] = pk2(a.z, a.w);
        return;
    }
    lb -= 4096;
    const float* W; __half* Wt; int Kd, Nd;
    if (lb < 4096)      { W = Wq;  Wt = WqT;  Kd = D; Nd = D;   }
    else if (lb < 6144) { W = Wr1; Wt = Wr1T; Kd = D; Nd = DH;  lb -= 4096; }
    else if (lb < 7168) { W = Wk;  Wt = WkT;  Kd = D; Nd = KVD; lb -= 6144; }
    else if (lb < 8192) { W = Wv;  Wt = WvT;  Kd = D; Nd = KVD; lb -= 7168; }
    else                { W = Wo;  Wt = WoT;  Kd = D; Nd = D;   lb -= 8192; }
    int ntn = Nd / 32;
    int nb = (lb % ntn) * 32, kb = (lb / ntn) * 32;
    int tx = tid & 31, ty0 = tid >> 5;
    #pragma unroll
    for (int i = 0; i < 4; i++)
        tile[ty0 + 8 * i][tx] = W[(size_t)(kb + ty0 + 8 * i) * Nd + nb + tx];
    __syncthreads();
    #pragma unroll
    for (int i = 0; i < 4; i++) {
        int r = ty0 + 8 * i;
        Wt[(size_t)(nb + r) * Kd + kb + tx] = __float2half_rn(tile[tx][r]);
    }
}

// ================= EMA pass 2 =================
__global__ void ema2_kernel(const float* __restrict__ carry, float* __restrict__ cpref) {
    int d = blockIdx.x * 256 + threadIdx.x;
    const float b128 = 1.3900845e-06f;  // 0.9^128
    float p = 0.f;
    #pragma unroll
    for (int c = 0; c < 16; c++) {
        cpref[c * D + d] = p;
        p = carry[c * D + d] + b128 * p;
    }
}

// ========== fp16 HMMA GEMM, quad-buffered, ONE sync per K-chunk ==========
#define SM_STRIDE 80
#define SM_SPLIT 10240
#define SM_BUF 20480
#define SMEMB 81920

template<int ACT>
__global__ __launch_bounds__(256, 2)
void gemm_mma(const __half* __restrict__ A, const __half* __restrict__ B,
              const float* __restrict__ bias, float* __restrict__ C,
              __half* __restrict__ Chi,
              int M, int N, int K,
              const __half* B2, float* C2, __half* C2hi) {
    extern __shared__ char smem[];
    if (blockIdx.z) { B = B2; C = C2; Chi = C2hi; }
    const int tid = threadIdx.x, wid = tid >> 5, lane = tid & 31;
    const int m0 = blockIdx.y * 128, n0 = blockIdx.x * 128;
    const int wm = wid >> 2, wn = wid & 3;
    const uint32_t sb = smem_u32(smem);

    const int r0c = tid >> 2, c0c = (tid & 3);
    const int r1c = (tid + 256) >> 2, c1c = (tid & 3);
    // per-thread global source bases (advance by 32 halves per chunk)
    const __half* ga0 = A + (size_t)(m0 + r0c) * K + c0c * 8;
    const __half* ga1 = A + (size_t)(m0 + r1c) * K + c1c * 8;
    const __half* gb0 = B + (size_t)(n0 + r0c) * K + c0c * 8;
    const __half* gb1 = B + (size_t)(n0 + r1c) * K + c1c * 8;
    const uint32_t so0 = r0c * SM_STRIDE + c0c * 16;
    const uint32_t so1 = r1c * SM_STRIDE + c1c * 16;

    auto fill = [&](int buf, int kc) {
        const int k0 = kc << 5;
        const uint32_t s0 = sb + buf * SM_BUF;
        CP16(s0 + so0, ga0 + k0);
        CP16(s0 + so1, ga1 + k0);
        CP16(s0 + SM_SPLIT + so0, gb0 + k0);
        CP16(s0 + SM_SPLIT + so1, gb1 + k0);
        CP_COMMIT();
    };

    // hoisted per-warp LDSM offsets (relative to buffer base)
    const uint32_t lrow = (lane & 15), lcol = (lane >> 4) * 16;
    uint32_t aoff[4], boff[2];
    #pragma unroll
    for (int mt = 0; mt < 4; mt++)
        aoff[mt] = (wm * 64 + mt * 16 + lrow) * SM_STRIDE + lcol;
    #pragma unroll
    for (int nt = 0; nt < 2; nt++)
        boff[nt] = SM_SPLIT + (wn * 32 + nt * 16 + lrow) * SM_STRIDE + lcol;

    float acc[4][4][4] = {};
    const int KC = K >> 5;
    fill(0, 0);
    fill(1, 1);
    fill(2, 2);
    for (int kc = 0; kc < KC; kc++) {
        if (kc + 2 < KC)      { CP_WAIT(2); }
        else if (kc + 1 < KC) { CP_WAIT(1); }
        else                  { CP_WAIT(0); }
        __syncthreads();
        if (kc + 3 < KC) fill((kc + 3) & 3, kc + 3);
        const uint32_t base = sb + (kc & 3) * SM_BUF;
        #pragma unroll
        for (int kh = 0; kh < 2; kh++) {
            uint32_t af[4][4], bf[2][4];
            #pragma unroll
            for (int mt = 0; mt < 4; mt++)
                ldsm_x4(af[mt], base + aoff[mt] + kh * 32);
            #pragma unroll
            for (int nt = 0; nt < 2; nt++)
                ldsm_x4(bf[nt], base + boff[nt] + kh * 32);
            #pragma unroll
            for (int mt = 0; mt < 4; mt++)
                #pragma unroll
                for (int j = 0; j < 4; j++)
                    mma16816(acc[mt][j], af[mt], bf[j >> 1][j & 1], bf[j >> 1][2 + (j & 1)]);
        }
    }

    const int erow = m0 + wm * 64 + (lane >> 2);
    const int ecol = n0 + wn * 32 + (lane & 3) * 2;
    #pragma unroll
    for (int mt = 0; mt < 4; mt++)
        #pragma unroll
        for (int j = 0; j < 4; j++) {
            int r = erow + mt * 16, c = ecol + j * 8;
            float v0 = acc[mt][j][0], v1 = acc[mt][j][1];
            float v2 = acc[mt][j][2], v3 = acc[mt][j][3];
            if (ACT) {
                float b0 = bias[c], b1 = bias[c + 1];
                v0 += b0; v1 += b1; v2 += b0; v3 += b1;
                v0 = v0 / (1.f + expf(-v0)); v1 = v1 / (1.f + expf(-v1));
                v2 = v2 / (1.f + expf(-v2)); v3 = v3 / (1.f + expf(-v3));
            }
            if (C) {
                *(float2*)(C + (size_t)r * N + c)       = make_float2(v0, v1);
                *(float2*)(C + (size_t)(r + 8) * N + c) = make_float2(v2, v3);
            }
            if (Chi) {
                *(uint32_t*)(Chi + (size_t)r * N + c)       = pk2(v0, v1);
                *(uint32_t*)(Chi + (size_t)(r + 8) * N + c) = pk2(v2, v3);
            }
        }
}

// ================= router + fuse (one block per token) =================
__global__ void router_fuse(const float* __restrict__ h, const float* __restrict__ Wr2,
                            const float* __restrict__ br2, const float* __restrict__ x,
                            const float* __restrict__ l2, const float* __restrict__ cpref,
                            __half* __restrict__ fh) {
    __shared__ float red[16];
    __shared__ float lamS[2];
    int t = blockIdx.x, tid = threadIdx.x, wid = tid >> 5, lane = tid & 31;
    const float* hp = h + (size_t)t * DH;
    float4 hv  = *(const float4*)(hp + tid * 4);
    float4 w01 = *(const float4*)(Wr2 + tid * 8);
    float4 w23 = *(const float4*)(Wr2 + tid * 8 + 4);
    float z0 = hv.x * w01.x + hv.y * w01.z + hv.z * w23.x + hv.w * w23.z;
    float z1 = hv.x * w01.y + hv.y * w01.w + hv.z * w23.y + hv.w * w23.w;
    #pragma unroll
    for (int off = 16; off; off >>= 1) {
        z0 += __shfl_xor_sync(0xffffffffu, z0, off);
        z1 += __shfl_xor_sync(0xffffffffu, z1, off);
    }
    if (lane == 0) { red[wid] = z0; red[8 + wid] = z1; }
    __syncthreads();
    if (tid == 0) {
        float a = 0.f, b = 0.f;
        #pragma unroll
        for (int i = 0; i < 8; i++) { a += red[i]; b += red[8 + i]; }
        a += br2[0]; b += br2[1];
        float mx = fmaxf(a, b);
        float e0 = expf(a - mx), e1 = expf(b - mx);
        float inv = 1.f / (e0 + e1);
        lamS[0] = e0 * inv; lamS[1] = e1 * inv;
    }
    __syncthreads();
    float la = lamS[0], lb = lamS[1];
    int c = t >> 7, tl = t & 127;
    float w = __expf((float)(tl + 1) * -0.10536051565f);
    size_t rowo = (size_t)t * D;
    #pragma unroll
    for (int i = 0; i < 2; i++) {
        int e = tid * 8 + i * 4;
        float4 xv = *(const float4*)(x + rowo + e);
        float4 lv = *(const float4*)(l2 + rowo + e);
        float4 cp = *(const float4*)(cpref + c * D + e);
        float f0 = la * xv.x + lb * (lv.x + w * cp.x);
        float f1 = la * xv.y + lb * (lv.y + w * cp.y);
        float f2 = la * xv.z + lb * (lv.z + w * cp.z);
        float f3 = la * xv.w + lb * (lv.w + w * cp.w);
        ((uint32_t*)fh)[(rowo + e) / 2]     = pk2(f0, f1);
        ((uint32_t*)fh)[(rowo + e) / 2 + 1] = pk2(f2, f3);
    }
}

// ================= RoPE (fp16 in, fp16 out) =================
__global__ void rope_h(const __half* __restrict__ x, __half* __restrict__ o, int heads) {
    int idx = blockIdx.x * blockDim.x + threadIdx.x;
    int total = T * heads * 32;
    if (idx >= total) return;
    int jp = idx & 31;
    int hh = (idx >> 5) % heads;
    int t = idx / (heads * 32);
    int j = jp * 2;
    const float LN = 0.1439115683121279f;  // ln(10000)/64
    float inv0 = expf(-LN * j), inv1 = expf(-LN * (j + 1));
    float c0, s0, c1, s1;
    sincosf((float)t * inv0, &s0, &c0);
    sincosf((float)t * inv1, &s1, &c1);
    size_t base = (size_t)t * heads * HD + hh * HD;
    __half2 plo = *(const __half2*)(x + base + j);
    __half2 phi = *(const __half2*)(x + base + j + 64);
    float a0 = __low2float(plo), a1 = __high2float(plo);
    float b0 = __low2float(phi), b1 = __high2float(phi);
    *(uint32_t*)(o + base + j)      = pk2(a0 * c0 - b0 * s0, a1 * c1 - b1 * s1);
    *(uint32_t*)(o + base + j + 64) = pk2(b0 * c0 + a0 * s0, b1 * c1 + a1 * s1);
}

// ===== tensor-core flash attention (256 thr, 128-row Q tile, pure fp16) =====
#define FA_STR 272
#define FA_QS 34816
#define FA_KS 17408
#define FA_KVB 34816
#define FA_KV0 34816
#define FA_SMEM 104448

__global__ __launch_bounds__(256, 1)
void fattn_kernel(const __half* __restrict__ Q, const __half* __restrict__ K,
                  const __half* __restrict__ V, __half* __restrict__ aoH) {
    extern __shared__ char smem[];
    const int tid = threadIdx.x, wid = tid >> 5, lane = tid & 31;
    const int qt = (int)(gridDim.x - 1 - blockIdx.x);   // long CTAs first
    const int head = blockIdx.y;
    const int kvh = head >> 2;
    const uint32_t sb = smem_u32(smem);
    const int g = lane >> 2, tq = lane & 3;
    const uint32_t lrow = lane & 15, lcol = (lane >> 4) * 16;

    {
        const size_t qoff = (size_t)(qt * 128) * D + head * HD;
        #pragma unroll
        for (int i = 0; i < 8; i++) {
            int idx = tid + i * 256;
            int r = idx >> 4, c = idx & 15;
            CP16(sb + r * FA_STR + c * 16, Q + qoff + (size_t)r * D + c * 8);
        }
        CP_COMMIT();
    }

    const int kts = 2 * qt + 2;
    auto loadKV = [&](int kt) {
        const size_t koff = (size_t)(kt * 64) * KVD + kvh * HD;
        const uint32_t kb = sb + FA_KV0 + (kt & 1) * FA_KVB;
        #pragma unroll
        for (int i = 0; i < 4; i++) {
            int idx = tid + i * 256;
            int r = idx >> 4, c = idx & 15;
            size_t so = koff + (size_t)r * KVD + c * 8;
            uint32_t dst = kb + r * FA_STR + c * 16;
            CP16(dst,         K + so);
            CP16(dst + FA_KS, V + so);
        }
        CP_COMMIT();
    };
    loadKV(0);

    float m0 = -1e30f, m1 = -1e30f, l0 = 0.f, l1 = 0.f;
    float oa[16][4] = {};
    const float SC2 = 0.08838834764831845f * 1.4426950408889634f;

    for (int kt = 0; kt < kts; kt++) {
        if (kt + 1 < kts) { loadKV(kt + 1); CP_WAIT(1); }
        else              { CP_WAIT(0); }
        __syncthreads();
        const uint32_t kb = sb + FA_KV0 + (kt & 1) * FA_KVB;

        float s[8][4];
        #pragma unroll
        for (int nf = 0; nf < 8; nf++)
            s[nf][0] = s[nf][1] = s[nf][2] = s[nf][3] = 0.f;
        #pragma unroll
        for (int ks = 0; ks < 8; ks++) {
            uint32_t af[4], bk[4][4];
            ldsm_x4(af, sb + (wid * 16 + lrow) * FA_STR + lcol + ks * 32);
            #pragma unroll
            for (int bt = 0; bt < 4; bt++)
                ldsm_x4(bk[bt], kb + (bt * 16 + lrow) * FA_STR + lcol + ks * 32);
            #pragma unroll
            for (int nf = 0; nf < 8; nf++)
                mma16816(s[nf], af, bk[nf >> 1][nf & 1], bk[nf >> 1][2 + (nf & 1)]);
        }

        if (kt >= kts - 2) {
            int rg = qt * 128 + wid * 16 + g;
            int kbase = kt * 64;
            #pragma unroll
            for (int nf = 0; nf < 8; nf++) {
                int cg = kbase + nf * 8 + tq * 2;
                if (cg > rg)         s[nf][0] = -1e30f;
                if (cg + 1 > rg)     s[nf][1] = -1e30f;
                if (cg > rg + 8)     s[nf][2] = -1e30f;
                if (cg + 1 > rg + 8) s[nf][3] = -1e30f;
            }
        }

        float mx0 = -1e30f, mx1 = -1e30f;
        #pragma unroll
        for (int nf = 0; nf < 8; nf++) {
            mx0 = fmaxf(mx0, fmaxf(s[nf][0], s[nf][1]));
            mx1 = fmaxf(mx1, fmaxf(s[nf][2], s[nf][3]));
        }
        mx0 = fmaxf(mx0, __shfl_xor_sync(0xffffffffu, mx0, 1));
        mx0 = fmaxf(mx0, __shfl_xor_sync(0xffffffffu, mx0, 2));
        mx1 = fmaxf(mx1, __shfl_xor_sync(0xffffffffu, mx1, 1));
        mx1 = fmaxf(mx1, __shfl_xor_sync(0xffffffffu, mx1, 2));
        float mn0 = fmaxf(m0, mx0), mn1 = fmaxf(m1, mx1);
        float corr0 = ex2((m0 - mn0) * SC2);
        float corr1 = ex2((m1 - mn1) * SC2);
        m0 = mn0; m1 = mn1;
        l0 *= corr0; l1 *= corr1;
        #pragma unroll
        for (int nf = 0; nf < 8; nf++) {
            s[nf][0] = ex2((s[nf][0] - m0) * SC2);
            s[nf][1] = ex2((s[nf][1] - m0) * SC2);
            s[nf][2] = ex2((s[nf][2] - m1) * SC2);
            s[nf][3] = ex2((s[nf][3] - m1) * SC2);
            l0 += s[nf][0] + s[nf][1];
            l1 += s[nf][2] + s[nf][3];
        }
        #pragma unroll
        for (int nf = 0; nf < 16; nf++) {
            oa[nf][0] *= corr0; oa[nf][1] *= corr0;
            oa[nf][2] *= corr1; oa[nf][3] *= corr1;
        }

        const uint32_t vb = kb + FA_KS;
        #pragma unroll
        for (int pk = 0; pk < 4; pk++) {
            uint32_t pa[4];
            pa[0] = pk2(s[2 * pk][0],     s[2 * pk][1]);
            pa[1] = pk2(s[2 * pk][2],     s[2 * pk][3]);
            pa[2] = pk2(s[2 * pk + 1][0], s[2 * pk + 1][1]);
            pa[3] = pk2(s[2 * pk + 1][2], s[2 * pk + 1][3]);
            #pragma unroll
            for (int nbp = 0; nbp < 4; nbp++) {
                int nb0 = 2 * nbp, nb1 = 2 * nbp + 1;
                uint32_t vh0[4], vh1[4];
                ldsm_x4_t(vh0, vb + (pk * 16 + lrow) * FA_STR + nb0 * 32 + lcol);
                ldsm_x4_t(vh1, vb + (pk * 16 + lrow) * FA_STR + nb1 * 32 + lcol);
                mma16816(oa[2 * nb0],     pa, vh0[0], vh0[1]);
                mma16816(oa[2 * nb0 + 1], pa, vh0[2], vh0[3]);
                mma16816(oa[2 * nb1],     pa, vh1[0], vh1[1]);
                mma16816(oa[2 * nb1 + 1], pa, vh1[2], vh1[3]);
            }
        }
        __syncthreads();
    }

    l0 += __shfl_xor_sync(0xffffffffu, l0, 1);
    l0 += __shfl_xor_sync(0xffffffffu, l0, 2);
    l1 += __shfl_xor_sync(0xffffffffu, l1, 1);
    l1 += __shfl_xor_sync(0xffffffffu, l1, 2);
    float inv0 = 1.f / l0, inv1 = 1.f / l1;
    int row0 = qt * 128 + wid * 16 + g;
    size_t base0 = (size_t)row0 * D + head * HD + tq * 2;
    size_t base1 = base0 + 8 * D;
    #pragma unroll
    for (int nf = 0; nf < 16; nf++) {
        *(uint32_t*)(aoH + base0 + nf * 8) = pk2(oa[nf][0] * inv0, oa[nf][1] * inv0);
        *(uint32_t*)(aoH + base1 + nf * 8) = pk2(oa[nf][2] * inv1, oa[nf][3] * inv1);
    }
}

// ================= launcher =================
extern "C" void kernel_launch(void* const* d_in, const int* in_sizes, int n_in,
                              void* d_out, int out_size) {
    const float* hs  = (const float*)d_in[0];
    const float* Wq  = (const float*)d_in[1];
    const float* Wk  = (const float*)d_in[2];
    const float* Wv  = (const float*)d_in[3];
    const float* Wo  = (const float*)d_in[4];
    const float* Wr1 = (const float*)d_in[5];
    const float* br1 = (const float*)d_in[6];
    const float* Wr2 = (const float*)d_in[7];
    const float* br2 = (const float*)d_in[8];
    float* out = (float*)d_out;

    float* S;
    cudaGetSymbolAddress((void**)&S, g_scratch);
    float* l2    = S;                        // [0,4M)
    float* h     = S + 4 * MEG;              // [4M,6M)
    float* lam   = S + 6 * MEG;
    float* carry = lam + 4096;
    float* cpref = carry + 32768;
    __half* hsH  = (__half*)(S + 7 * MEG);
    __half* qH   = (__half*)(S + 9 * MEG);
    __half* fusH = (__half*)(S + 11 * MEG);
    __half* WqT  = (__half*)(S + 13 * MEG);
    __half* Wr1T = (__half*)(S + 15 * MEG);
    __half* WkT  = (__half*)(S + 16 * MEG);
    __half* WvT  = (__half*)(S + 16 * MEG + 512 * 1024);
    __half* WoT  = (__half*)(S + 17 * MEG);
    __half* kH   = (__half*)(S + 19 * MEG);
    __half* VH   = (__half*)(S + 19 * MEG + 512 * 1024);
    __half* QrH  = (__half*)(S + 20 * MEG);
    __half* KrH  = (__half*)(S + 22 * MEG);
    __half* aoH  = (__half*)(S + 23 * MEG);

    cudaFuncSetAttribute(gemm_mma<0>, cudaFuncAttributeMaxDynamicSharedMemorySize, SMEMB);
    cudaFuncSetAttribute(gemm_mma<1>, cudaFuncAttributeMaxDynamicSharedMemorySize, SMEMB);
    cudaFuncSetAttribute(fattn_kernel, cudaFuncAttributeMaxDynamicSharedMemorySize, FA_SMEM);

    // ---- prep: ema1 + hs fp16 + all weight transposes (one launch) ----
    prep_kernel<<<16512, 256>>>(hs, Wq, Wr1, Wk, Wv, Wo,
                                WqT, Wr1T, WkT, WvT, WoT, hsH, l2, carry);
    ema2_kernel<<<8, 256>>>(carry, cpref);

    // ---- q = hs @ Wq (fp16 out only) ----
    gemm_mma<0><<<dim3(D / 128, T / 128, 1), 256, SMEMB>>>(
        hsH, WqT, nullptr, nullptr, qH, T, D, D, nullptr, nullptr, nullptr);

    // ---- h = silu(q @ Wr1 + br1) (fp32 out) ----
    gemm_mma<1><<<dim3(DH / 128, T / 128, 1), 256, SMEMB>>>(
        qH, Wr1T, br1, h, nullptr, T, DH, D, nullptr, nullptr, nullptr);

    // ---- router + fuse -> fp16 fused ----
    router_fuse<<<T, 256>>>(h, Wr2, br2, hs, l2, cpref, fusH);

    // ---- k/v = fused @ Wk/Wv (fp16 out only) ----
    gemm_mma<0><<<dim3(KVD / 128, T / 128, 2), 256, SMEMB>>>(
        fusH, WkT, nullptr, nullptr, kH, T, KVD, D, WvT, nullptr, VH);

    // ---- RoPE (fp16 in/out) ----
    rope_h<<<(T * NH * 32 + 255) / 256, 256>>>(qH, QrH, NH);
    rope_h<<<(T * NKVH * 32 + 255) / 256, 256>>>(kH, KrH, NKVH);

    // ---- flash attention -> fp16 aoH ----
    fattn_kernel<<<dim3(T / 128, NH), 256, FA_SMEM>>>(QrH, KrH, VH, aoH);

    // ---- out = ao @ Wo (fp32 out) ----
    gemm_mma<0><<<dim3(D / 128, T / 128, 1), 256, SMEMB>>>(
        aoH, WoT, nullptr, out, nullptr, T, D, D, nullptr, nullptr, nullptr);
}